// round 11
// baseline (speedup 1.0000x reference)
#include <cuda_runtime.h>
#include <math_constants.h>

#define NPTS 4096
#define WARPS_PER_BLOCK 28
#define NTHREADS 896
#define NBLOCKS 147
#define FULL 0xffffffffu

#define GDIM 64
#define GCELLS (GDIM * GDIM)
#define BHALF 5.0f
#define CW 0.15625f                           // 10/64, exact in fp32
#define INVW 6.4f

// persistent grid (device globals; zero-initialized at module load)
__device__ __align__(16) unsigned g_cnt[GCELLS];
__device__ __align__(16) unsigned g_st[GCELLS + 8];   // exclusive starts (+pad)
__device__ __align__(16) unsigned g_cur[GCELLS];      // scatter cursors
__device__ __align__(16) float    g_px[NPTS];
__device__ __align__(16) float    g_py[NPTS];
__device__ __align__(16) int      g_idx[NPTS];

__device__ __forceinline__ int cellof(float v) {
    int c = (int)floorf((v + BHALF) * INVW);
    return min(max(c, 0), GDIM - 1);
}

__device__ __forceinline__ bool pless(float da, int ia, float db, int ib) {
    return (da < db) || (da == db && ia < ib);
}
#define CAS(dx, ix, dy, iy)                                  \
    do { if (!pless(dx, ix, dy, iy)) {                       \
        float _t = dx; dx = dy; dy = _t;                     \
        int _u = ix; ix = iy; iy = _u; } } while (0)
#define CASV(a, b) do { float _lo = fminf(a, b), _hi = fmaxf(a, b); a = _lo; b = _hi; } while (0)

// ---------------- K1: histogram ----------------
__global__ void hist_kernel(const float2* __restrict__ obs2) {
    int j = blockIdx.x * blockDim.x + threadIdx.x;
    if (j < NPTS) {
        float2 p = obs2[j];
        atomicAdd(&g_cnt[cellof(p.y) * GDIM + cellof(p.x)], 1u);
    }
}

// ---------------- K2: scan (1 block, 1024 thr) + restore cnt=0 ----------------
__global__ void __launch_bounds__(1024) scan_kernel() {
    __shared__ unsigned wsum[32];
    const int t = threadIdx.x;
    const int lane = t & 31, wid = t >> 5;

    uint4 c = ((const uint4*)g_cnt)[t];       // cells 4t..4t+3
    unsigned s = c.x + c.y + c.z + c.w;
    unsigned inc = s;
    #pragma unroll
    for (int off = 1; off < 32; off <<= 1) {
        unsigned v = __shfl_up_sync(FULL, inc, off);
        if (lane >= off) inc += v;
    }
    if (lane == 31) wsum[wid] = inc;
    __syncthreads();
    if (wid == 0) {
        unsigned v = wsum[lane];
        #pragma unroll
        for (int off = 1; off < 32; off <<= 1) {
            unsigned u = __shfl_up_sync(FULL, v, off);
            if (lane >= off) v += u;
        }
        wsum[lane] = v;
    }
    __syncthreads();
    unsigned base = (wid ? wsum[wid - 1] : 0u) + (inc - s);
    uint4 o;
    o.x = base;
    o.y = base + c.x;
    o.z = base + c.x + c.y;
    o.w = base + c.x + c.y + c.z;
    ((uint4*)g_st)[t]  = o;
    ((uint4*)g_cur)[t] = o;
    ((uint4*)g_cnt)[t] = make_uint4(0u, 0u, 0u, 0u);   // ready for next call
    if (t == 0) {
        g_st[GCELLS]     = NPTS;
        g_st[GCELLS + 1] = NPTS; g_st[GCELLS + 2] = NPTS; g_st[GCELLS + 3] = NPTS;
    }
}

// ---------------- K3: scatter into cell-sorted order ----------------
__global__ void scatter_kernel(const float2* __restrict__ obs2) {
    int j = blockIdx.x * blockDim.x + threadIdx.x;
    if (j < NPTS) {
        float2 p = obs2[j];
        int c = cellof(p.y) * GDIM + cellof(p.x);
        unsigned pos = atomicAdd(&g_cur[c], 1u);
        g_px[pos] = p.x; g_py[pos] = p.y; g_idx[pos] = j;
    }
}

// ---------------- K4: query ----------------
// smem: ssx[4096] ssy[4096] sidx[4096] st[4100]
#define Q_SMEM_WORDS (NPTS * 3 + GCELLS + 4)
#define Q_SMEM_BYTES (Q_SMEM_WORDS * 4)

extern __shared__ unsigned q_smem[];

__global__ void __launch_bounds__(NTHREADS)
query_kernel(const float2* __restrict__ obs1,
             const float2* __restrict__ obs2,
             const float*  __restrict__ W,
             const float*  __restrict__ bias,
             float* __restrict__ out)
{
    float*    ssx  = (float*)q_smem;
    float*    ssy  = ssx + NPTS;
    int*      sidx = (int*)(ssy + NPTS);
    unsigned* st   = (unsigned*)(sidx + NPTS);   // 4100 words

    const int tid  = threadIdx.x;
    const int warp = tid >> 5;
    const int lane = tid & 31;

    // stage grid into smem (uint4 copies)
    for (int t = tid; t < NPTS / 4; t += NTHREADS) {
        ((uint4*)ssx)[t]  = ((const uint4*)g_px)[t];
        ((uint4*)ssy)[t]  = ((const uint4*)g_py)[t];
        ((uint4*)sidx)[t] = ((const uint4*)g_idx)[t];
    }
    for (int t = tid; t < (GCELLS + 4) / 4; t += NTHREADS)
        ((uint4*)st)[t] = ((const uint4*)g_st)[t];
    __syncthreads();

    const int i = blockIdx.x * WARPS_PER_BLOCK + warp;
    if (i >= NPTS) return;                     // no __syncthreads below

    const float2 qv = obs2[i];
    const float qx = qv.x, qy = qv.y;
    const int cx = cellof(qx), cy = cellof(qy);

    float d0 = CUDART_INF_F, d1 = CUDART_INF_F, d2 = CUDART_INF_F, d3 = CUDART_INF_F;
    int   i0 = 0x7fffffff,  i1 = 0x7fffffff,  i2 = 0x7fffffff,  i3 = 0x7fffffff;

    auto span = [&](int r, int ca, int cb) {   // contiguous candidate range
        unsigned p0 = st[r * GDIM + ca];
        unsigned p1 = st[r * GDIM + cb + 1];
        for (unsigned base = p0; base < p1; base += 32) {
            unsigned p = base + lane;
            if (p < p1) {
                float x = ssx[p], y = ssy[p];
                int   j = sidx[p];
                float ddx = x - qx, ddy = y - qy;
                float dv = fmaf(ddx, ddx, fmaf(ddy, ddy, 1.0f));
                if (j != i && pless(dv, j, d3, i3)) {
                    d3 = dv; i3 = j;
                    if (pless(d3,i3,d2,i2)) { float t=d3; d3=d2; d2=t; int u=i3; i3=i2; i2=u; }
                    if (pless(d2,i2,d1,i1)) { float t=d2; d2=d1; d1=t; int u=i2; i2=i1; i1=u; }
                    if (pless(d1,i1,d0,i0)) { float t=d1; d1=d0; d0=t; int u=i1; i1=i0; i0=u; }
                }
            }
        }
    };

    auto warp4th = [&]() -> float {            // exact 4th-smallest dist value
        float e0 = d0, e1 = d1, e2 = d2, e3 = d3;
        #pragma unroll
        for (int off = 16; off >= 1; off >>= 1) {
            float f0 = __shfl_xor_sync(FULL, e0, off);
            float f1 = __shfl_xor_sync(FULL, e1, off);
            float f2 = __shfl_xor_sync(FULL, e2, off);
            float f3 = __shfl_xor_sync(FULL, e3, off);
            float m0 = fminf(e0, f3);
            float m1 = fminf(e1, f2);
            float m2 = fminf(e2, f1);
            float m3 = fminf(e3, f0);
            CASV(m0, m2); CASV(m1, m3); CASV(m0, m1); CASV(m2, m3);
            e0 = m0; e1 = m1; e2 = m2; e3 = m3;
        }
        return e3;
    };

    // rings 0..1 merged: clipped 3x3 neighborhood (disjoint from k>=2 rings)
    bool done;
    {
        const int rl = max(cy - 1, 0), rh = min(cy + 1, GDIM - 1);
        const int cl = max(cx - 1, 0), cr = min(cx + 1, GDIM - 1);
        for (int r = rl; r <= rh; ++r) span(r, cl, cr);
        float kw = CW * 0.999f;                // after ring 1: unseen dist >= 1*W
        done = (fmaf(kw, kw, 1.0f) > warp4th());
    }

    if (!done) {
        for (int k = 2; k < GDIM; ++k) {
            const int rlo = cy - k, rhi = cy + k;
            const int cl = max(cx - k, 0), cr = min(cx + k, GDIM - 1);
            if (rlo >= 0) span(rlo, cl, cr);               // top row of ring
            if (rhi < GDIM) span(rhi, cl, cr);             // bottom row
            {   // side columns, middle rows
                const int rl = max(rlo + 1, 0), rh = min(rhi - 1, GDIM - 1);
                const bool lv = (cx - k) >= 0, rv = (cx + k) < GDIM;
                for (int r = rl; r <= rh; ++r) {
                    if (lv) span(r, cx - k, cx - k);
                    if (rv) span(r, cx + k, cx + k);
                }
            }
            float kw = (float)k * CW * 0.999f;
            if (fmaf(kw, kw, 1.0f) > warp4th()) break;
        }
    }

    // final indexed butterfly: 32 private sorted-4 -> warp-uniform top-4
    #pragma unroll
    for (int off = 16; off >= 1; off >>= 1) {
        float f0 = __shfl_xor_sync(FULL, d0, off);
        float f1 = __shfl_xor_sync(FULL, d1, off);
        float f2 = __shfl_xor_sync(FULL, d2, off);
        float f3 = __shfl_xor_sync(FULL, d3, off);
        int   g0 = __shfl_xor_sync(FULL, i0, off);
        int   g1 = __shfl_xor_sync(FULL, i1, off);
        int   g2 = __shfl_xor_sync(FULL, i2, off);
        int   g3 = __shfl_xor_sync(FULL, i3, off);

        float m0, m1, m2, m3; int n0, n1, n2, n3;
        if (pless(d0, i0, f3, g3)) { m0 = d0; n0 = i0; } else { m0 = f3; n0 = g3; }
        if (pless(d1, i1, f2, g2)) { m1 = d1; n1 = i1; } else { m1 = f2; n1 = g2; }
        if (pless(d2, i2, f1, g1)) { m2 = d2; n2 = i2; } else { m2 = f1; n2 = g1; }
        if (pless(d3, i3, f0, g0)) { m3 = d3; n3 = i3; } else { m3 = f0; n3 = g0; }

        CAS(m0, n0, m2, n2); CAS(m1, n1, m3, n3);
        CAS(m0, n0, m1, n1); CAS(m2, n2, m3, n3);

        d0 = m0; d1 = m1; d2 = m2; d3 = m3;
        i0 = n0; i1 = n1; i2 = n2; i3 = n3;
    }

    // epilogue: lane kk*8+o -> channel o of neighbor kk
    const int o = lane & 7;
    const float w0 = W[o * 6 + 0];
    const float w1 = W[o * 6 + 1];
    const float w3 = W[o * 6 + 3];
    const float w4 = W[o * 6 + 4];
    const float cb = W[o * 6 + 2] + W[o * 6 + 5] + bias[o];

    const int kk = lane >> 3;
    const int j = (kk == 0) ? i0 : (kk == 1) ? i1 : (kk == 2) ? i2 : i3;

    const float2 pj  = obs2[j];
    const float2 a1j = obs1[j];
    const float2 a1i = obs1[i];

    const float px = pj.x - qx;
    const float py = pj.y - qy;
    const float vx = (pj.x - a1j.x) - (qx - a1i.x);   // vel[j] - vel[i]
    const float vy = (pj.y - a1j.y) - (qy - a1i.y);

    float r = fmaf(px, w0, fmaf(py, w1, fmaf(vx, w3, fmaf(vy, w4, cb))));
    out[i * 32 + lane] = fmaxf(r, 0.0f);
}

extern "C" void kernel_launch(void* const* d_in, const int* in_sizes, int n_in,
                              void* d_out, int out_size) {
    const float2* obs1 = (const float2*)d_in[0];
    const float2* obs2 = (const float2*)d_in[1];
    const float*  Wp   = (const float*)d_in[2];
    const float*  bias = (const float*)d_in[3];
    float* out = (float*)d_out;

    static bool attr_set = false;
    if (!attr_set) {
        cudaFuncSetAttribute(query_kernel,
                             cudaFuncAttributeMaxDynamicSharedMemorySize, Q_SMEM_BYTES);
        attr_set = true;
    }

    hist_kernel<<<8, 512>>>(obs2);             // g_cnt assumed 0 (invariant)
    scan_kernel<<<1, 1024>>>();                // builds st/cur, re-zeros g_cnt
    scatter_kernel<<<8, 512>>>(obs2);
    query_kernel<<<NBLOCKS, NTHREADS, Q_SMEM_BYTES>>>(obs1, obs2, Wp, bias, out);
}

// round 12
// speedup vs baseline: 1.3787x; 1.3787x over previous
#include <cuda_runtime.h>
#include <math_constants.h>

#define NPTS 4096
#define WARPS_PER_BLOCK 28
#define NTHREADS 896
#define NBLOCKS 147
#define FULL 0xffffffffu

#define GDIM 64
#define GCELLS (GDIM * GDIM)
#define BHALF 5.0f
#define CW 0.15625f                           // 10/64, exact in fp32
#define INVW 6.4f

// persistent grid (device globals)
__device__ __align__(16) unsigned g_st[GCELLS + 4];   // exclusive starts + pad
__device__ __align__(16) float    g_px[NPTS];
__device__ __align__(16) float    g_py[NPTS];
__device__ __align__(16) int      g_idx[NPTS];

__device__ __forceinline__ int cellof(float v) {
    int c = (int)floorf((v + BHALF) * INVW);
    return min(max(c, 0), GDIM - 1);
}
__device__ __forceinline__ bool pless(float da, int ia, float db, int ib) {
    return (da < db) || (da == db && ia < ib);
}
#define CAS(dx, ix, dy, iy)                                  \
    do { if (!pless(dx, ix, dy, iy)) {                       \
        float _t = dx; dx = dy; dy = _t;                     \
        int _u = ix; ix = iy; iy = _u; } } while (0)
#define CASV(a, b) do { float _lo = fminf(a, b), _hi = fmaxf(a, b); a = _lo; b = _hi; } while (0)

// ---------------- K1: single-block build (hist + scan + scatter) ------------
__global__ void __launch_bounds__(1024) build_kernel(const float2* __restrict__ obs2) {
    __shared__ __align__(16) unsigned cnt[GCELLS];    // counts, then cursors
    __shared__ unsigned wsum[32];
    const int t = threadIdx.x;
    const int lane = t & 31, wid = t >> 5;

    // load 4 points/thread into registers (coalesced)
    float px[4], py[4]; int cell[4];
    #pragma unroll
    for (int u = 0; u < 4; ++u) {
        float2 p = obs2[t + u * 1024];
        px[u] = p.x; py[u] = p.y;
        cell[u] = cellof(p.y) * GDIM + cellof(p.x);
    }
    #pragma unroll
    for (int u = 0; u < 4; ++u) cnt[t + u * 1024] = 0u;
    __syncthreads();
    #pragma unroll
    for (int u = 0; u < 4; ++u) atomicAdd(&cnt[cell[u]], 1u);
    __syncthreads();

    // exclusive scan over 4096 counts (4 cells/thread)
    uint4 c = ((const uint4*)cnt)[t];
    unsigned s = c.x + c.y + c.z + c.w;
    unsigned inc = s;
    #pragma unroll
    for (int off = 1; off < 32; off <<= 1) {
        unsigned v = __shfl_up_sync(FULL, inc, off);
        if (lane >= off) inc += v;
    }
    if (lane == 31) wsum[wid] = inc;
    __syncthreads();
    if (wid == 0) {
        unsigned v = wsum[lane];
        #pragma unroll
        for (int off = 1; off < 32; off <<= 1) {
            unsigned u = __shfl_up_sync(FULL, v, off);
            if (lane >= off) v += u;
        }
        wsum[lane] = v;
    }
    __syncthreads();
    unsigned base = (wid ? wsum[wid - 1] : 0u) + (inc - s);
    uint4 o;
    o.x = base;
    o.y = base + c.x;
    o.z = o.y + c.y;
    o.w = o.z + c.z;
    ((uint4*)g_st)[t] = o;                     // starts -> global (for query)
    ((uint4*)cnt)[t]  = o;                     // cursors -> smem (reads done: sync'd)
    __syncthreads();

    // scatter from registers into cell-sorted global arrays
    #pragma unroll
    for (int u = 0; u < 4; ++u) {
        unsigned pos = atomicAdd(&cnt[cell[u]], 1u);
        g_px[pos] = px[u]; g_py[pos] = py[u]; g_idx[pos] = t + u * 1024;
    }
    if (t == 0) {
        g_st[GCELLS] = NPTS; g_st[GCELLS + 1] = NPTS;
        g_st[GCELLS + 2] = NPTS; g_st[GCELLS + 3] = NPTS;
    }
}

// ---------------- K2: query ----------------
#define Q_SMEM_WORDS (NPTS * 3 + GCELLS + 4)
#define Q_SMEM_BYTES (Q_SMEM_WORDS * 4)

extern __shared__ unsigned q_smem[];

__global__ void __launch_bounds__(NTHREADS)
query_kernel(const float2* __restrict__ obs1,
             const float2* __restrict__ obs2,
             const float*  __restrict__ W,
             const float*  __restrict__ bias,
             float* __restrict__ out)
{
    float*    ssx  = (float*)q_smem;
    float*    ssy  = ssx + NPTS;
    int*      sidx = (int*)(ssy + NPTS);
    unsigned* st   = (unsigned*)(sidx + NPTS);

    const int tid  = threadIdx.x;
    const int warp = tid >> 5;
    const int lane = tid & 31;

    for (int t = tid; t < NPTS / 4; t += NTHREADS) {
        ((uint4*)ssx)[t]  = ((const uint4*)g_px)[t];
        ((uint4*)ssy)[t]  = ((const uint4*)g_py)[t];
        ((uint4*)sidx)[t] = ((const uint4*)g_idx)[t];
    }
    for (int t = tid; t < (GCELLS + 4) / 4; t += NTHREADS)
        ((uint4*)st)[t] = ((const uint4*)g_st)[t];
    __syncthreads();

    const int i = blockIdx.x * WARPS_PER_BLOCK + warp;
    if (i >= NPTS) return;                     // no __syncthreads below

    const float2 qv = obs2[i];
    const float qx = qv.x, qy = qv.y;
    const int cx = cellof(qx), cy = cellof(qy);

    float d0 = CUDART_INF_F, d1 = CUDART_INF_F, d2 = CUDART_INF_F, d3 = CUDART_INF_F;
    int   i0 = 0x7fffffff,  i1 = 0x7fffffff,  i2 = 0x7fffffff,  i3 = 0x7fffffff;

    auto spanPQ = [&](unsigned p0, unsigned p1) {
        for (unsigned base = p0; base < p1; base += 32) {
            unsigned p = base + lane;
            if (p < p1) {
                float x = ssx[p], y = ssy[p];
                int   j = sidx[p];
                float ddx = x - qx, ddy = y - qy;
                float dv = fmaf(ddx, ddx, fmaf(ddy, ddy, 1.0f));
                if (j != i && pless(dv, j, d3, i3)) {
                    d3 = dv; i3 = j;
                    if (pless(d3,i3,d2,i2)) { float t=d3; d3=d2; d2=t; int u=i3; i3=i2; i2=u; }
                    if (pless(d2,i2,d1,i1)) { float t=d2; d2=d1; d1=t; int u=i2; i2=i1; i1=u; }
                    if (pless(d1,i1,d0,i0)) { float t=d1; d1=d0; d0=t; int u=i1; i1=i0; i0=u; }
                }
            }
        }
    };
    auto span = [&](int r, int ca, int cb) {
        spanPQ(st[r * GDIM + ca], st[r * GDIM + cb + 1]);
    };
    auto warp4th = [&]() -> float {            // exact 4th-smallest dist value
        float e0 = d0, e1 = d1, e2 = d2, e3 = d3;
        #pragma unroll
        for (int off = 16; off >= 1; off >>= 1) {
            float f0 = __shfl_xor_sync(FULL, e0, off);
            float f1 = __shfl_xor_sync(FULL, e1, off);
            float f2 = __shfl_xor_sync(FULL, e2, off);
            float f3 = __shfl_xor_sync(FULL, e3, off);
            float m0 = fminf(e0, f3);
            float m1 = fminf(e1, f2);
            float m2 = fminf(e2, f1);
            float m3 = fminf(e3, f0);
            CASV(m0, m2); CASV(m1, m3); CASV(m0, m1); CASV(m2, m3);
            e0 = m0; e1 = m1; e2 = m2; e3 = m3;
        }
        return e3;
    };

    // ---- common path: clipped 3x3, ALL bounds prefetched up-front ----
    bool done;
    {
        const int rl = max(cy - 1, 0), rh = min(cy + 1, GDIM - 1);
        const int cl = max(cx - 1, 0), cr = min(cx + 1, GDIM - 1);
        const int r1 = rl + 1, r2 = rl + 2;
        const bool h1 = (r1 <= rh), h2 = (r2 <= rh);
        // issue all bound loads before any gather (break LDS chains)
        unsigned a0 = st[rl * GDIM + cl],            a1 = st[rl * GDIM + cr + 1];
        unsigned b0 = h1 ? st[r1 * GDIM + cl]     : 0u;
        unsigned b1 = h1 ? st[r1 * GDIM + cr + 1] : 0u;
        unsigned c0 = h2 ? st[r2 * GDIM + cl]     : 0u;
        unsigned c1 = h2 ? st[r2 * GDIM + cr + 1] : 0u;
        spanPQ(a0, a1);
        spanPQ(b0, b1);
        spanPQ(c0, c1);
        float kw = CW * 0.999f;                // unseen points: dist >= 1*W
        done = (fmaf(kw, kw, 1.0f) > warp4th());
    }

    if (!done) {                               // rare: expanding square rings
        for (int k = 2; k < GDIM; ++k) {
            const int rlo = cy - k, rhi = cy + k;
            const int cl = max(cx - k, 0), cr = min(cx + k, GDIM - 1);
            if (rlo >= 0) span(rlo, cl, cr);
            if (rhi < GDIM) span(rhi, cl, cr);
            {
                const int rl = max(rlo + 1, 0), rh = min(rhi - 1, GDIM - 1);
                const bool lv = (cx - k) >= 0, rv = (cx + k) < GDIM;
                for (int r = rl; r <= rh; ++r) {
                    if (lv) span(r, cx - k, cx - k);
                    if (rv) span(r, cx + k, cx + k);
                }
            }
            float kw = (float)k * CW * 0.999f;
            if (fmaf(kw, kw, 1.0f) > warp4th()) break;
        }
    }

    // final indexed butterfly: 32 private sorted-4 -> warp-uniform top-4
    #pragma unroll
    for (int off = 16; off >= 1; off >>= 1) {
        float f0 = __shfl_xor_sync(FULL, d0, off);
        float f1 = __shfl_xor_sync(FULL, d1, off);
        float f2 = __shfl_xor_sync(FULL, d2, off);
        float f3 = __shfl_xor_sync(FULL, d3, off);
        int   g0 = __shfl_xor_sync(FULL, i0, off);
        int   g1 = __shfl_xor_sync(FULL, i1, off);
        int   g2 = __shfl_xor_sync(FULL, i2, off);
        int   g3 = __shfl_xor_sync(FULL, i3, off);

        float m0, m1, m2, m3; int n0, n1, n2, n3;
        if (pless(d0, i0, f3, g3)) { m0 = d0; n0 = i0; } else { m0 = f3; n0 = g3; }
        if (pless(d1, i1, f2, g2)) { m1 = d1; n1 = i1; } else { m1 = f2; n1 = g2; }
        if (pless(d2, i2, f1, g1)) { m2 = d2; n2 = i2; } else { m2 = f1; n2 = g1; }
        if (pless(d3, i3, f0, g0)) { m3 = d3; n3 = i3; } else { m3 = f0; n3 = g0; }

        CAS(m0, n0, m2, n2); CAS(m1, n1, m3, n3);
        CAS(m0, n0, m1, n1); CAS(m2, n2, m3, n3);

        d0 = m0; d1 = m1; d2 = m2; d3 = m3;
        i0 = n0; i1 = n1; i2 = n2; i3 = n3;
    }

    // epilogue: lane kk*8+o -> channel o of neighbor kk
    const int o = lane & 7;
    const float w0 = W[o * 6 + 0];
    const float w1 = W[o * 6 + 1];
    const float w3 = W[o * 6 + 3];
    const float w4 = W[o * 6 + 4];
    const float cb = W[o * 6 + 2] + W[o * 6 + 5] + bias[o];

    const int kk = lane >> 3;
    const int j = (kk == 0) ? i0 : (kk == 1) ? i1 : (kk == 2) ? i2 : i3;

    const float2 pj  = obs2[j];
    const float2 a1j = obs1[j];
    const float2 a1i = obs1[i];

    const float px = pj.x - qx;
    const float py = pj.y - qy;
    const float vx = (pj.x - a1j.x) - (qx - a1i.x);   // vel[j] - vel[i]
    const float vy = (pj.y - a1j.y) - (qy - a1i.y);

    float r = fmaf(px, w0, fmaf(py, w1, fmaf(vx, w3, fmaf(vy, w4, cb))));
    out[i * 32 + lane] = fmaxf(r, 0.0f);
}

extern "C" void kernel_launch(void* const* d_in, const int* in_sizes, int n_in,
                              void* d_out, int out_size) {
    const float2* obs1 = (const float2*)d_in[0];
    const float2* obs2 = (const float2*)d_in[1];
    const float*  Wp   = (const float*)d_in[2];
    const float*  bias = (const float*)d_in[3];
    float* out = (float*)d_out;

    cudaFuncSetAttribute(query_kernel,
                         cudaFuncAttributeMaxDynamicSharedMemorySize, Q_SMEM_BYTES);

    build_kernel<<<1, 1024>>>(obs2);
    query_kernel<<<NBLOCKS, NTHREADS, Q_SMEM_BYTES>>>(obs1, obs2, Wp, bias, out);
}

// round 13
// speedup vs baseline: 2.9375x; 2.1307x over previous
#include <cuda_runtime.h>
#include <math_constants.h>

#define NPTS 4096
#define SEEDN 512                             // seed prefix length
#define WARPS_PER_BLOCK 28
#define NTHREADS (WARPS_PER_BLOCK * 32)      // 896
#define NBLOCKS 147                           // 1 block/SM
#define FULL 0xffffffffu

__device__ __forceinline__ bool pless(float da, int ia, float db, int ib) {
    return (da < db) || (da == db && ia < ib);
}
#define CAS(dx, ix, dy, iy)                                  \
    do { if (!pless(dx, ix, dy, iy)) {                       \
        float _t = dx; dx = dy; dy = _t;                     \
        int _u = ix; ix = iy; iy = _u; } } while (0)

__device__ __forceinline__ void ins4(float dv, int j,
                                     float& d0, float& d1, float& d2, float& d3,
                                     int& i0, int& i1, int& i2, int& i3) {
    // strictly increasing j per lane + strict '<' => exact top_k tie order
    d3 = dv; i3 = j;
    if (d3 < d2) { float t=d3; d3=d2; d2=t; int u=i3; i3=i2; i2=u; }
    if (d2 < d1) { float t=d2; d2=d1; d1=t; int u=i2; i2=i1; i1=u; }
    if (d1 < d0) { float t=d1; d1=d0; d0=t; int u=i1; i1=i0; i0=u; }
}

__global__ void __launch_bounds__(NTHREADS)
nn_tag_pool_kernel(const float2* __restrict__ obs1,
                   const float2* __restrict__ obs2,
                   const float*  __restrict__ W,
                   const float*  __restrict__ bias,
                   float* __restrict__ out)
{
    __shared__ __align__(16) float sx[NPTS];
    __shared__ __align__(16) float sy[NPTS];

    const int tid = threadIdx.x;
    {   // stage + deinterleave: obs2 AoS float2 -> SoA sx/sy
        const float4* g4 = (const float4*)obs2;
        for (int m = tid; m < NPTS / 2; m += NTHREADS) {
            float4 v = g4[m];                 // {x0,y0,x1,y1}
            sx[2*m]   = v.x;  sy[2*m]   = v.y;
            sx[2*m+1] = v.z;  sy[2*m+1] = v.w;
        }
    }
    __syncthreads();

    const int warp = tid >> 5;
    const int lane = tid & 31;
    const int i = blockIdx.x * WARPS_PER_BLOCK + warp;   // query row
    if (i >= NPTS) return;                    // whole tail warps only

    const float qx = sx[i], qy = sy[i];

    const float4* sx4 = (const float4*)sx;
    const float4* sy4 = (const float4*)sy;

    // ---------- seed: per-lane private top-4 over 16 pts of [0,512) ----------
    float d0 = CUDART_INF_F, d1 = CUDART_INF_F, d2 = CUDART_INF_F, d3 = CUDART_INF_F;
    int   i0 = 0x7fffffff,  i1 = 0x7fffffff,  i2 = 0x7fffffff,  i3 = 0x7fffffff;

    #pragma unroll
    for (int u = 0; u < 4; ++u) {             // strided: conflict-free LDS.128
        float4 X = sx4[u * 32 + lane];
        float4 Y = sy4[u * 32 + lane];
        const int jb = (u * 32 + lane) * 4;
        #pragma unroll
        for (int h = 0; h < 4; ++h) {
            float px = (h == 0) ? X.x : (h == 1) ? X.y : (h == 2) ? X.z : X.w;
            float py = (h == 0) ? Y.x : (h == 1) ? Y.y : (h == 2) ? Y.z : Y.w;
            float ddx = px - qx, ddy = py - qy;
            float dv = fmaf(ddx, ddx, fmaf(ddy, ddy, 1.0f));
            int j = jb + h;                   // ascending j within lane
            if (j != i && dv < d3)
                ins4(dv, j, d0, d1, d2, d3, i0, i1, i2, i3);
        }
    }

    // indexed butterfly merge: 32 private sorted-4 -> warp-uniform top-4 of [0,512)
    #pragma unroll
    for (int off = 16; off >= 1; off >>= 1) {
        float f0 = __shfl_xor_sync(FULL, d0, off);
        float f1 = __shfl_xor_sync(FULL, d1, off);
        float f2 = __shfl_xor_sync(FULL, d2, off);
        float f3 = __shfl_xor_sync(FULL, d3, off);
        int   g0 = __shfl_xor_sync(FULL, i0, off);
        int   g1 = __shfl_xor_sync(FULL, i1, off);
        int   g2 = __shfl_xor_sync(FULL, i2, off);
        int   g3 = __shfl_xor_sync(FULL, i3, off);

        float m0, m1, m2, m3; int n0, n1, n2, n3;
        if (pless(d0, i0, f3, g3)) { m0 = d0; n0 = i0; } else { m0 = f3; n0 = g3; }
        if (pless(d1, i1, f2, g2)) { m1 = d1; n1 = i1; } else { m1 = f2; n1 = g2; }
        if (pless(d2, i2, f1, g1)) { m2 = d2; n2 = i2; } else { m2 = f1; n2 = g1; }
        if (pless(d3, i3, f0, g0)) { m3 = d3; n3 = i3; } else { m3 = f0; n3 = g0; }

        CAS(m0, n0, m2, n2); CAS(m1, n1, m3, n3);
        CAS(m0, n0, m1, n1); CAS(m2, n2, m3, n3);

        d0 = m0; d1 = m1; d2 = m2; d3 = m3;
        i0 = n0; i1 = n1; i2 = n2; i3 = n3;
    }
    // list now warp-uniform and EXACT over [0,512); d3 = tight threshold

    // ---------- main scan: [512,4096), 7 superiters of 512 points ----------
    #pragma unroll 2
    for (int s = 0; s < (NPTS - SEEDN) / 512; ++s) {
        const int b4 = (SEEDN / 4) + s * 128 + lane;   // float4 base
        float v[16];
        float mg0, mg1, mg2, mg3;

        #pragma unroll
        for (int g = 0; g < 4; ++g) {
            float4 X = sx4[b4 + g * 32];
            float4 Y = sy4[b4 + g * 32];
            float dxa = X.x - qx, dya = Y.x - qy;
            float dxb = X.y - qx, dyb = Y.y - qy;
            float dxc = X.z - qx, dyc = Y.z - qy;
            float dxd = X.w - qx, dyd = Y.w - qy;
            v[g*4+0] = fmaf(dxa, dxa, fmaf(dya, dya, 1.0f));
            v[g*4+1] = fmaf(dxb, dxb, fmaf(dyb, dyb, 1.0f));
            v[g*4+2] = fmaf(dxc, dxc, fmaf(dyc, dyc, 1.0f));
            v[g*4+3] = fmaf(dxd, dxd, fmaf(dyd, dyd, 1.0f));
            float m = fminf(fminf(v[g*4+0], v[g*4+1]), fminf(v[g*4+2], v[g*4+3]));
            if (g == 0) mg0 = m; else if (g == 1) mg1 = m;
            else if (g == 2) mg2 = m; else mg3 = m;
        }

        float mall = fminf(fminf(mg0, mg1), fminf(mg2, mg3));

        // ONE ballot + ONE branch per 512 points (common path)
        if (__ballot_sync(FULL, mall < d3)) {
            #pragma unroll
            for (int g = 0; g < 4; ++g) {
                float mg = (g == 0) ? mg0 : (g == 1) ? mg1 : (g == 2) ? mg2 : mg3;
                unsigned mk = __ballot_sync(FULL, mg < d3);
                while (mk) {                   // warp-uniform, rare
                    int r = __ffs(mk) - 1;
                    mk &= mk - 1;
                    float x0 = __shfl_sync(FULL, v[g*4+0], r);
                    float x1 = __shfl_sync(FULL, v[g*4+1], r);
                    float x2 = __shfl_sync(FULL, v[g*4+2], r);
                    float x3 = __shfl_sync(FULL, v[g*4+3], r);
                    int jb = SEEDN + s * 512 + g * 128 + 4 * r;   // ascending

                    if (jb + 0 != i && x0 < d3) ins4(x0, jb + 0, d0,d1,d2,d3, i0,i1,i2,i3);
                    if (jb + 1 != i && x1 < d3) ins4(x1, jb + 1, d0,d1,d2,d3, i0,i1,i2,i3);
                    if (jb + 2 != i && x2 < d3) ins4(x2, jb + 2, d0,d1,d2,d3, i0,i1,i2,i3);
                    if (jb + 3 != i && x3 < d3) ins4(x3, jb + 3, d0,d1,d2,d3, i0,i1,i2,i3);

                    if (mk) mk &= __ballot_sync(FULL, mg < d3);  // refilter
                }
            }
        }
    }

    // ---------- epilogue: list warp-uniform; lane kk*8+o -> channel o ------
    const int o = lane & 7;
    const float w0 = W[o * 6 + 0];
    const float w1 = W[o * 6 + 1];
    const float w3 = W[o * 6 + 3];
    const float w4 = W[o * 6 + 4];
    const float cb = W[o * 6 + 2] + W[o * 6 + 5] + bias[o];

    const int kk = lane >> 3;
    const int j = (kk == 0) ? i0 : (kk == 1) ? i1 : (kk == 2) ? i2 : i3;

    const float pjx = sx[j], pjy = sy[j];
    const float2 a1j = obs1[j];
    const float2 a1i = obs1[i];

    const float px = pjx - qx;
    const float py = pjy - qy;
    const float vx = (pjx - a1j.x) - (qx - a1i.x);   // vel[j] - vel[i]
    const float vy = (pjy - a1j.y) - (qy - a1i.y);

    float r = fmaf(px, w0, fmaf(py, w1, fmaf(vx, w3, fmaf(vy, w4, cb))));
    out[i * 32 + lane] = fmaxf(r, 0.0f);
}

extern "C" void kernel_launch(void* const* d_in, const int* in_sizes, int n_in,
                              void* d_out, int out_size) {
    const float2* obs1 = (const float2*)d_in[0];
    const float2* obs2 = (const float2*)d_in[1];
    const float*  Wp   = (const float*)d_in[2];
    const float*  bias = (const float*)d_in[3];
    float* out = (float*)d_out;

    nn_tag_pool_kernel<<<NBLOCKS, NTHREADS>>>(obs1, obs2, Wp, bias, out);
}